// round 14
// baseline (speedup 1.0000x reference)
#include <cuda_runtime.h>
#include <math.h>

#define FULLMASK 0xffffffffu
#define Bn   64
#define Wn   128
#define Fn   132
#define An   128
#define TGTn 3
#define En   8
#define HIDn 16
#define OUTn 128
#define NROW (Bn*Wn)

typedef unsigned long long u64;

// ---------------- scratch (device globals; no allocation) ----------------
__device__ float g_Lo[NROW*En];
__device__ float g_Ro[NROW*En];
__device__ float g_y[2*NROW*128];
__device__ float g_part2[2][256][2][16];
__device__ unsigned g_bar;            // monotonic epoch counter (zero-init)
__device__ float g_xw0[NROW*48];
__device__ float g_h1fin[Bn*HIDn];

// HW-approx activations
__device__ __forceinline__ float tanh_a(float x) {
    float y; asm("tanh.approx.f32 %0, %1;" : "=f"(y) : "f"(x)); return y;
}
__device__ __forceinline__ float sigm_a(float x) { return fmaf(0.5f, tanh_a(0.5f * x), 0.5f); }
__device__ __forceinline__ float ex2_a(float x) {
    float y; asm("ex2.approx.f32 %0, %1;" : "=f"(y) : "f"(x)); return y;
}

// packed f32x2 helpers
__device__ __forceinline__ u64 pack2(float lo, float hi) {
    u64 r; asm("mov.b64 %0, {%1,%2};" : "=l"(r) : "f"(lo), "f"(hi)); return r;
}
__device__ __forceinline__ void unpack2(u64 v, float& lo, float& hi) {
    asm("mov.b64 {%0,%1}, %2;" : "=f"(lo), "=f"(hi) : "l"(v));
}
__device__ __forceinline__ u64 ffma2(u64 a, u64 b, u64 c) {
    u64 d; asm("fma.rn.f32x2 %0, %1, %2, %3;" : "=l"(d) : "l"(a), "l"(b), "l"(c)); return d;
}

__device__ __forceinline__ float dotp8b(const u64* w, const u64* h, u64 bias2, u64 zero2) {
    u64 a = ffma2(w[0], h[0], bias2);
    u64 b = ffma2(w[1], h[1], zero2);
    a = ffma2(w[2], h[2], a); b = ffma2(w[3], h[3], b);
    a = ffma2(w[4], h[4], a); b = ffma2(w[5], h[5], b);
    a = ffma2(w[6], h[6], a); b = ffma2(w[7], h[7], b);
    float al, ah, bl, bh;
    unpack2(a, al, ah); unpack2(b, bl, bh);
    return (al + ah) + (bl + bh);
}

__device__ __forceinline__ float dotp4b(const u64* w, const u64* h, u64 bias2, u64 zero2) {
    u64 a = ffma2(w[0], h[0], bias2);
    u64 b = ffma2(w[1], h[1], zero2);
    a = ffma2(w[2], h[2], a);
    b = ffma2(w[3], h[3], b);
    float al, ah, bl, bh;
    unpack2(a, al, ah); unpack2(b, bl, bh);
    return (al + ah) + (bl + bh);
}

#define GCHUNK 8
#define GNCH   (Wn / GCHUNK)

// ============================================================================
// K1 fused (verbatim R13): blocks 0..127 gate GRU v3 (2-warp); 128..383 GEMM.
// ============================================================================
#define GE1_SMEM_BYTES ((64*129 + 128) * 4)
__global__ void __launch_bounds__(256) k_ge1(
    const float* __restrict__ Local, const float* __restrict__ Remote,
    const float* __restrict__ Wih0, const float* __restrict__ Whh0,
    const float* __restrict__ bih0, const float* __restrict__ bhh0,
    const float* __restrict__ Wih1, const float* __restrict__ Whh1,
    const float* __restrict__ bih1, const float* __restrict__ bhh1,
    const float* __restrict__ w1,   const float* __restrict__ b1)
{
    extern __shared__ float smdyn[];

    if (blockIdx.x < 128) {
        if (threadIdx.x >= 64) return;
        __shared__ __align__(16) float sh0[8];
        __shared__ __align__(16) float sh1[8];
        float* sring = smdyn;

        const int tid  = threadIdx.x;
        const int wid  = tid >> 5;
        const int lane = tid & 31;
        const int side = blockIdx.x >> 6;
        const int b    = blockIdx.x & 63;
        const float* in  = side ? Remote : Local;
        float*       out = side ? g_Ro   : g_Lo;

        const int j    = lane & 7;
        const bool isZ = (lane >= 8)  && (lane < 16);
        const bool isN = (lane >= 16) && (lane < 24);
        const int rowA = (isZ || isN) ? lane : 0;
        const int rowB = j;
        const float scA = isZ ? 0.5f : 1.0f;
        const u64 Z2 = pack2(0.f, 0.f);

        if (wid == 0) {
            u64 uA0p[4], uB0p[4], wiA1p[4], wiB1p[4];
            float wxA[3], wxB[3];
            u64 bA0_2, bB0_2, biA1_2, biB1_2;
            float biA0 = 0.f, biB0 = 0.f;
            {
                float tA[8], tB[8];
#pragma unroll
                for (int k = 0; k < 8; k++) {
                    tA[k] = (isZ || isN) ? scA * Whh0[rowA*8+k] : 0.f;
                    tB[k] = isN ? 0.5f * Whh0[rowB*8+k] : 0.f;
                }
#pragma unroll
                for (int k = 0; k < 4; k++) {
                    uA0p[k] = pack2(tA[2*k], tA[2*k+1]);
                    uB0p[k] = pack2(tB[2*k], tB[2*k+1]);
                }
#pragma unroll
                for (int k = 0; k < 8; k++) {
                    tA[k] = (isZ || isN) ? scA * Wih1[rowA*8+k] : 0.f;
                    tB[k] = isN ? 0.5f * Wih1[rowB*8+k] : 0.f;
                }
#pragma unroll
                for (int k = 0; k < 4; k++) {
                    wiA1p[k] = pack2(tA[2*k], tA[2*k+1]);
                    wiB1p[k] = pack2(tB[2*k], tB[2*k+1]);
                }
#pragma unroll
                for (int c = 0; c < 3; c++) {
                    wxA[c] = (isZ || isN) ? scA * Wih0[rowA*3+c] : 0.f;
                    wxB[c] = isN ? 0.5f * Wih0[rowB*3+c] : 0.f;
                }
                biA0 = (isZ || isN) ? scA * bih0[rowA] : 0.f;
                biB0 = isN ? 0.5f * bih0[rowB] : 0.f;
                bA0_2 = pack2((isZ || isN) ? scA * bhh0[rowA] : 0.f, 0.f);
                bB0_2 = pack2(isN ? 0.5f * bhh0[rowB] : 0.f, 0.f);
                biA1_2 = pack2((isZ || isN) ? scA * bih1[rowA] : 0.f, 0.f);
                biB1_2 = pack2(isN ? 0.5f * bih1[rowB] : 0.f, 0.f);
            }

            if (isZ) sh0[j] = 0.f;
            __syncwarp();
            float h0own = 0.f;

            u64 H0c[4];
            {
                ulonglong2 q0 = *(const ulonglong2*)(sh0);
                ulonglong2 q1 = *(const ulonglong2*)(sh0 + 4);
                H0c[0]=q0.x; H0c[1]=q0.y; H0c[2]=q1.x; H0c[3]=q1.y;
            }

            const float* px = in + (size_t)b * Wn * Fn + An;
            float xc0[GCHUNK], xc1[GCHUNK], xc2[GCHUNK];
            float xn0[GCHUNK], xn1[GCHUNK], xn2[GCHUNK];
#pragma unroll
            for (int k = 0; k < GCHUNK; k++) {
                const float* p = px + (size_t)k * Fn;
                xc0[k] = p[0]; xc1[k] = p[1]; xc2[k] = p[2];
            }

            for (int c = 0; c < GNCH; c++) {
                {
                    int base = ((c + 1) & (GNCH - 1)) * GCHUNK;
#pragma unroll
                    for (int k = 0; k < GCHUNK; k++) {
                        const float* p = px + (size_t)(base + k) * Fn;
                        xn0[k] = p[0]; xn1[k] = p[1]; xn2[k] = p[2];
                    }
                }
#pragma unroll
                for (int k = 0; k < GCHUNK; k++) {
                    const int t = c * GCHUNK + k;
                    float ghA = dotp4b(uA0p, H0c, bA0_2, Z2);
                    float ghB = dotp4b(uB0p, H0c, bB0_2, Z2);
                    float xwA = fmaf(wxA[0], xc0[k], fmaf(wxA[1], xc1[k], fmaf(wxA[2], xc2[k], biA0)));
                    float xwB = fmaf(wxB[0], xc0[k], fmaf(wxB[1], xc1[k], fmaf(wxB[2], xc2[k], biB0)));
                    float preS = isN ? (xwB + ghB) : (xwA + ghA);
                    float s = fmaf(0.5f, tanh_a(preS), 0.5f);
                    float nv = tanh_a(fmaf(s, ghA, xwA));
                    float nvz = __shfl_sync(FULLMASK, nv, lane + 8);
                    if (isZ) {
                        h0own = fmaf(s, h0own - nvz, nvz);
                        sh0[j] = h0own;
                    }
                    __syncwarp();
                    {
                        ulonglong2 q0 = *(const ulonglong2*)(sh0);
                        ulonglong2 q1 = *(const ulonglong2*)(sh0 + 4);
                        H0c[0]=q0.x; H0c[1]=q0.y; H0c[2]=q1.x; H0c[3]=q1.y;
                    }
                    float xwA1 = dotp4b(wiA1p, H0c, biA1_2, Z2);
                    float xwB1 = dotp4b(wiB1p, H0c, biB1_2, Z2);
                    sring[t * 64 + lane] = xwA1;
                    if (isN) sring[t * 64 + 32 + j] = xwB1;
                }
#pragma unroll
                for (int k = 0; k < GCHUNK; k++) { xc0[k]=xn0[k]; xc1[k]=xn1[k]; xc2[k]=xn2[k]; }
                __syncthreads();
            }
        } else {
            u64 uA1p[4], uB1p[4];
            u64 bhA1_2, bhB1_2;
            {
                float tA[8], tB[8];
#pragma unroll
                for (int k = 0; k < 8; k++) {
                    tA[k] = (isZ || isN) ? scA * Whh1[rowA*8+k] : 0.f;
                    tB[k] = isN ? 0.5f * Whh1[rowB*8+k] : 0.f;
                }
#pragma unroll
                for (int k = 0; k < 4; k++) {
                    uA1p[k] = pack2(tA[2*k], tA[2*k+1]);
                    uB1p[k] = pack2(tB[2*k], tB[2*k+1]);
                }
                bhA1_2 = pack2((isZ || isN) ? scA * bhh1[rowA] : 0.f, 0.f);
                bhB1_2 = pack2(isN ? 0.5f * bhh1[rowB] : 0.f, 0.f);
            }

            if (isZ) sh1[j] = 0.f;
            __syncwarp();
            float h1own = 0.f;

            u64 H1c[4];
            {
                ulonglong2 r0 = *(const ulonglong2*)(sh1);
                ulonglong2 r1 = *(const ulonglong2*)(sh1 + 4);
                H1c[0]=r0.x; H1c[1]=r0.y; H1c[2]=r1.x; H1c[3]=r1.y;
            }

            for (int c = 0; c < GNCH; c++) {
                __syncthreads();
#pragma unroll
                for (int k = 0; k < GCHUNK; k++) {
                    const int t = c * GCHUNK + k;
                    float xwA1 = sring[t * 64 + lane];
                    float xwB1 = sring[t * 64 + 32 + j];
                    float ghA1 = dotp4b(uA1p, H1c, bhA1_2, Z2);
                    float ghB1 = dotp4b(uB1p, H1c, bhB1_2, Z2);
                    float preS1 = isN ? (xwB1 + ghB1) : (xwA1 + ghA1);
                    float s1 = fmaf(0.5f, tanh_a(preS1), 0.5f);
                    float nv1 = tanh_a(fmaf(s1, ghA1, xwA1));
                    float nvz1 = __shfl_sync(FULLMASK, nv1, lane + 8);
                    if (isZ) {
                        h1own = fmaf(s1, h1own - nvz1, nvz1);
                        sh1[j] = h1own;
                    }
                    __syncwarp();
                    {
                        ulonglong2 r0 = *(const ulonglong2*)(sh1);
                        ulonglong2 r1 = *(const ulonglong2*)(sh1 + 4);
                        H1c[0]=r0.x; H1c[1]=r0.y; H1c[2]=r1.x; H1c[3]=r1.y;
                    }
                    float myh = sh1[j];
                    float ex = ex2_a(myh * 1.44269504f);
                    float ssum = ex;
                    ssum += __shfl_xor_sync(FULLMASK, ssum, 1);
                    ssum += __shfl_xor_sync(FULLMASK, ssum, 2);
                    ssum += __shfl_xor_sync(FULLMASK, ssum, 4);
                    if (lane < 8)
                        out[((size_t)b * Wn + t) * En + lane] = ex * __frcp_rn(ssum);
                }
            }
        }
        return;
    }

    // ---------------- per-expert GEMM path (verbatim) ----------------
    float* sx  = smdyn;
    float* sb1 = sx + 64 * 129;

    const int gid  = blockIdx.x - 128;
    const int side = gid >> 7;
    const int tile = gid & 127;
    const int n0   = tile * 64;
    const float* in = side ? Remote : Local;
    const int tid   = threadIdx.x;

    for (int i = tid; i < 64 * 128; i += 256) {
        int r = i >> 7, c = i & 127;
        sx[r * 129 + c] = in[(size_t)(n0 + r) * Fn + c];
    }
    if (tid < 128) sb1[tid] = b1[tid];
    __syncthreads();

    const int rg = tid >> 4, cg = tid & 15;
    const int r0 = rg * 4, c0 = cg * 8;
    const int e  = c0 >> 4, hb = c0 & 15;
    const float* wbase = w1 + e * 2048 + hb;

    u64 acc[4][4];
    {
        u64 i0 = pack2(sb1[c0+0], sb1[c0+1]);
        u64 i1 = pack2(sb1[c0+2], sb1[c0+3]);
        u64 i2 = pack2(sb1[c0+4], sb1[c0+5]);
        u64 i3 = pack2(sb1[c0+6], sb1[c0+7]);
#pragma unroll
        for (int jj = 0; jj < 4; jj++) { acc[jj][0]=i0; acc[jj][1]=i1; acc[jj][2]=i2; acc[jj][3]=i3; }
    }

#pragma unroll 2
    for (int k = 0; k < 128; k++) {
        float xv0 = sx[(r0+0)*129 + k];
        float xv1 = sx[(r0+1)*129 + k];
        float xv2 = sx[(r0+2)*129 + k];
        float xv3 = sx[(r0+3)*129 + k];
        ulonglong2 wA = *(const ulonglong2*)(wbase + k*16);
        ulonglong2 wB = *(const ulonglong2*)(wbase + k*16 + 4);
        u64 x0 = pack2(xv0, xv0), x1 = pack2(xv1, xv1);
        u64 x2 = pack2(xv2, xv2), x3 = pack2(xv3, xv3);
        acc[0][0]=ffma2(x0,wA.x,acc[0][0]); acc[0][1]=ffma2(x0,wA.y,acc[0][1]);
        acc[0][2]=ffma2(x0,wB.x,acc[0][2]); acc[0][3]=ffma2(x0,wB.y,acc[0][3]);
        acc[1][0]=ffma2(x1,wA.x,acc[1][0]); acc[1][1]=ffma2(x1,wA.y,acc[1][1]);
        acc[1][2]=ffma2(x1,wB.x,acc[1][2]); acc[1][3]=ffma2(x1,wB.y,acc[1][3]);
        acc[2][0]=ffma2(x2,wA.x,acc[2][0]); acc[2][1]=ffma2(x2,wA.y,acc[2][1]);
        acc[2][2]=ffma2(x2,wB.x,acc[2][2]); acc[2][3]=ffma2(x2,wB.y,acc[2][3]);
        acc[3][0]=ffma2(x3,wA.x,acc[3][0]); acc[3][1]=ffma2(x3,wA.y,acc[3][1]);
        acc[3][2]=ffma2(x3,wB.x,acc[3][2]); acc[3][3]=ffma2(x3,wB.y,acc[3][3]);
    }

#pragma unroll
    for (int jj = 0; jj < 4; jj++) {
        float* yrow = g_y + ((size_t)side * NROW + n0 + r0 + jj) * 128 + c0;
        ulonglong2 v0; v0.x = acc[jj][0]; v0.y = acc[jj][1];
        ulonglong2 v1; v1.x = acc[jj][2]; v1.y = acc[jj][3];
        *(ulonglong2*)(yrow)     = v0;
        *(ulonglong2*)(yrow + 4) = v1;
    }
}

// ============================================================================
// K2 (NEW, merged comb+exp2): per-block h from g_y, deterministic BN partials,
// grid spin-barrier (ticketed epoch counter), then BN+elu / layer-2 GEMM /
// mixer projection. __launch_bounds__(256,2) guarantees 296 >= 256 resident.
// ============================================================================
__global__ void __launch_bounds__(256, 2) k_cexp2(
    const float* __restrict__ w2, const float* __restrict__ b2,
    const float* __restrict__ aeg, const float* __restrict__ aebt,
    const float* __restrict__ Wih0m, const float* __restrict__ bih0m)
{
    __shared__ float sW2T[16*132];
    __shared__ float sb2[128];
    __shared__ float sWp[768];
    __shared__ float sbi[48];
    __shared__ float sg[16], sbt[16];
    __shared__ float sstat[64];
    __shared__ float su[32*136];
    __shared__ float sz[32*20];
    __shared__ float s_hL[32][16];
    __shared__ float s_hR[32][16];
    __shared__ float s_red[64];

    const int tid = threadIdx.x;
    const int bx  = blockIdx.x;
    const int n0  = bx * 32;

    for (int i = tid; i < 2048; i += 256) {
        int ii = i >> 4, o = i & 15;
        sW2T[o * 132 + ii] = w2[i];
    }
    for (int i = tid; i < 768; i += 256) sWp[i] = Wih0m[i];
    if (tid < 128) sb2[tid] = b2[tid];
    if (tid < 48)  sbi[tid] = bih0m[tid];
    if (tid < 16)  { sg[tid] = aeg[tid]; sbt[tid] = aebt[tid]; }

    const int r   = tid >> 3;      // 0..31
    const int p   = tid & 7;
    const int h0i = 2 * p;
    const int n   = n0 + r;

    // ---- phase 0: h for our rows (order matches old comb) ----
    float oL[8], oR[8];
    {
        float4 a = *(const float4*)(g_Lo + (size_t)n * 8);
        float4 b = *(const float4*)(g_Lo + (size_t)n * 8 + 4);
        oL[0]=a.x; oL[1]=a.y; oL[2]=a.z; oL[3]=a.w; oL[4]=b.x; oL[5]=b.y; oL[6]=b.z; oL[7]=b.w;
        float4 c = *(const float4*)(g_Ro + (size_t)n * 8);
        float4 d = *(const float4*)(g_Ro + (size_t)n * 8 + 4);
        oR[0]=c.x; oR[1]=c.y; oR[2]=c.z; oR[3]=c.w; oR[4]=d.x; oR[5]=d.y; oR[6]=d.z; oR[7]=d.w;
    }
    {
        const float* yL = g_y + (size_t)n * 128;
        const float* yR = g_y + ((size_t)NROW + n) * 128;
        float aL0=0.f, aL1=0.f, aR0=0.f, aR1=0.f;
#pragma unroll
        for (int e = 0; e < 8; e++) {
            float2 vL = *(const float2*)(yL + e*16 + h0i);
            float2 vR = *(const float2*)(yR + e*16 + h0i);
            aL0 = fmaf(oL[e], vL.x, aL0); aL1 = fmaf(oL[e], vL.y, aL1);
            aR0 = fmaf(oR[e], vR.x, aR0); aR1 = fmaf(oR[e], vR.y, aR1);
        }
        s_hL[r][h0i] = aL0; s_hL[r][h0i+1] = aL1;
        s_hR[r][h0i] = aR0; s_hR[r][h0i+1] = aR1;
    }
    __syncthreads();

    // ---- block BN partials (deterministic serial over 32 rows) ----
    if (tid < 64) {
        int side = tid >> 5, h = (tid >> 1) & 15, w = tid & 1;
        const float (*sh_)[16] = side ? s_hR : s_hL;
        float a = 0.f;
#pragma unroll 4
        for (int rr = 0; rr < 32; rr++) {
            float v = sh_[rr][h];
            a = w ? fmaf(v, v, a) : (a + v);
        }
        g_part2[side][bx][w][h] = a;
    }
    __threadfence();
    __syncthreads();

    // ---- grid spin-barrier (ticketed epoch) ----
    if (tid == 0) {
        unsigned t = atomicAdd(&g_bar, 1u);
        unsigned target = (t / 256u) * 256u + 256u;
        while (*(volatile unsigned*)&g_bar < target) { }
    }
    __syncthreads();
    __threadfence();

    // ---- reduce partials (deterministic order 0..255) ----
    if (tid < 64) {
        int side = tid >> 5, h = (tid >> 1) & 15, w = tid & 1;
        float a = 0.f;
#pragma unroll 4
        for (int c = 0; c < 256; c++) a += g_part2[side][c][w][h];
        s_red[tid] = a;
    }
    __syncthreads();
    if (tid < 32) {
        int side = tid >> 4, h = tid & 15;
        float s = s_red[side * 32 + h * 2 + 0];
        float q = s_red[side * 32 + h * 2 + 1];
        float mean = s * (1.0f / NROW);
        float var  = q * (1.0f / NROW) - mean * mean;
        sstat[side * 32 + h]      = mean;
        sstat[side * 32 + 16 + h] = rsqrtf(var + 1e-5f);
    }
    __syncthreads();

    {   // phase A: build u (h from smem)
        float hlx = s_hL[r][h0i], hly = s_hL[r][h0i+1];
        float hrx = s_hR[r][h0i], hry = s_hR[r][h0i+1];
        float vL0 = fmaf(sg[h0i]   * (hlx - sstat[h0i]),        sstat[16+h0i],   sbt[h0i]);
        float vL1 = fmaf(sg[h0i+1] * (hly - sstat[h0i+1]),      sstat[16+h0i+1], sbt[h0i+1]);
        float vR0 = fmaf(sg[h0i]   * (hrx - sstat[32+h0i]),     sstat[48+h0i],   sbt[h0i]);
        float vR1 = fmaf(sg[h0i+1] * (hry - sstat[32+h0i+1]),   sstat[48+h0i+1], sbt[h0i+1]);
        vL0 = (vL0 > 0.f) ? vL0 : (__expf(vL0) - 1.0f);
        vL1 = (vL1 > 0.f) ? vL1 : (__expf(vL1) - 1.0f);
        vR0 = (vR0 > 0.f) ? vR0 : (__expf(vR0) - 1.0f);
        vR1 = (vR1 > 0.f) ? vR1 : (__expf(vR1) - 1.0f);
        float* ur = su + r * 136;
#pragma unroll
        for (int e = 0; e < 8; e++) {
            ur[e*16 + h0i]     = fmaf(oL[e], vL0, oR[e] * vR0);
            ur[e*16 + h0i + 1] = fmaf(oL[e], vL1, oR[e] * vR1);
        }
        if (p == 0) {
#pragma unroll
            for (int e = 0; e < 8; e++) ur[128 + e] = oL[e] + oR[e];
        }
    }
    __syncthreads();

    {   // phase B
        const int g2 = tid >> 4, o = tid & 15;
        const int ra = 2 * g2, rb = ra + 1;
        float acc0 = 0.f, acc1 = 0.f;
        const float* osA = su + ra * 136 + 128;
        const float* osB = su + rb * 136 + 128;
#pragma unroll
        for (int e = 0; e < 8; e++) {
            float w = sb2[e * 16 + o];
            acc0 = fmaf(osA[e], w, acc0);
            acc1 = fmaf(osB[e], w, acc1);
        }
        const float* wrow = sW2T + o * 132;
        const float* uA = su + ra * 136;
        const float* uB = su + rb * 136;
#pragma unroll 4
        for (int i = 0; i < 128; i += 4) {
            float4 w = *(const float4*)(wrow + i);
            float4 a = *(const float4*)(uA + i);
            float4 b = *(const float4*)(uB + i);
            acc0 = fmaf(a.x, w.x, acc0); acc1 = fmaf(b.x, w.x, acc1);
            acc0 = fmaf(a.y, w.y, acc0); acc1 = fmaf(b.y, w.y, acc1);
            acc0 = fmaf(a.z, w.z, acc0); acc1 = fmaf(b.z, w.z, acc1);
            acc0 = fmaf(a.w, w.w, acc0); acc1 = fmaf(b.w, w.w, acc1);
        }
        sz[ra * 20 + o] = acc0;
        sz[rb * 20 + o] = acc1;
    }
    __syncthreads();

    {   // phase C
        const int sl = tid & 7;
        float zv[16];
        const float4* zp = (const float4*)(sz + r * 20);
#pragma unroll
        for (int q4 = 0; q4 < 4; q4++) {
            float4 v = zp[q4];
            zv[q4*4+0]=v.x; zv[q4*4+1]=v.y; zv[q4*4+2]=v.z; zv[q4*4+3]=v.w;
        }
        float* dst = g_xw0 + (size_t)n * 48 + sl * 6;
#pragma unroll
        for (int jo = 0; jo < 6; jo++) {
            int o = sl * 6 + jo;
            const float* wr = sWp + o * 16;
            float a = sbi[o], bsum = 0.f;
#pragma unroll
            for (int k = 0; k < 16; k += 2) {
                a    = fmaf(zv[k],   wr[k],   a);
                bsum = fmaf(zv[k+1], wr[k+1], bsum);
            }
            dst[jo] = a + bsum;
        }
    }
}

// ============================================================================
// K3 (v7): mixer GRU, THREE-warp pipeline.
//   W0: layer-0 recurrence -> h0 ring
//   W1: xw1 projection (h0 ring -> xw ring)
//   W2: layer-1 recurrence (xw ring) -> g_h1fin
// Depth-2 chunked pipeline, 18 uniform __syncthreads. Arithmetic identical
// per value to R12/R13 mixer.
// ============================================================================
#define MCHUNK 8
#define MNCH   (Wn / MCHUNK)
__global__ void __launch_bounds__(96) k_mixer(
    const float* __restrict__ Whh0, const float* __restrict__ bhh0,
    const float* __restrict__ Wih1, const float* __restrict__ bih1,
    const float* __restrict__ Whh1, const float* __restrict__ bhh1)
{
    __shared__ __align__(16) float s_h0w[32];
    __shared__ __align__(16) float s_h1w[32];
    __shared__ __align__(16) float s_h0r[Wn][16];
    __shared__ float s_xw[Wn][48];

    const int tid  = threadIdx.x;
    const int wid  = tid >> 5;
    const int lane = tid & 31;
    const int b    = blockIdx.x;
    const int rowS = lane;
    const int rowN = 32 + (lane & 15);
    const u64 Z2 = pack2(0.f, 0.f);

    if (wid == 0) {
        // ---- W0: layer-0 ----
        u64 uS0[8], uN0[8];
        {
            const u64* pp;
            pp = (const u64*)(Whh0 + rowS * 16);
#pragma unroll
            for (int k = 0; k < 8; k++) uS0[k] = pp[k];
            pp = (const u64*)(Whh0 + rowN * 16);
#pragma unroll
            for (int k = 0; k < 8; k++) uN0[k] = pp[k];
        }
        const u64 bS0_2 = pack2(bhh0[rowS], 0.f);
        const u64 bN0_2 = pack2(bhh0[rowN], 0.f);

        s_h0w[lane] = 0.f;
        __syncwarp();
        float h0own = 0.f;

        u64 H0c[8];
#pragma unroll
        for (int k = 0; k < 8; k++) H0c[k] = Z2;

        const float* xp = g_xw0 + (size_t)b * Wn * 48;
        float xcS[MCHUNK], xcN[MCHUNK], xnS[MCHUNK], xnN[MCHUNK];
#pragma unroll
        for (int k = 0; k < MCHUNK; k++) {
            xcS[k] = xp[(size_t)k * 48 + rowS];
            xcN[k] = xp[(size_t)k * 48 + rowN];
        }

        for (int it = 0; it < MNCH + 2; it++) {
            if (it < MNCH) {
                {
                    int base = ((it + 1) & (MNCH - 1)) * MCHUNK;
#pragma unroll
                    for (int k = 0; k < MCHUNK; k++) {
                        xnS[k] = xp[(size_t)(base + k) * 48 + rowS];
                        xnN[k] = xp[(size_t)(base + k) * 48 + rowN];
                    }
                }
#pragma unroll
                for (int k = 0; k < MCHUNK; k++) {
                    const int t = it * MCHUNK + k;
                    float ghS0 = dotp8b(uS0, H0c, bS0_2, Z2);
                    float ghN0 = dotp8b(uN0, H0c, bN0_2, Z2);
                    float s0  = sigm_a(xcS[k] + ghS0);
                    float nv0 = tanh_a(fmaf(s0, ghN0, xcN[k]));
                    float z0  = __shfl_sync(FULLMASK, s0, 16 + (lane & 15));
                    h0own = fmaf(z0, h0own - nv0, nv0);
                    s_h0w[lane] = h0own;
                    __syncwarp();
                    {
                        ulonglong2 q0 = *(const ulonglong2*)(s_h0w);
                        ulonglong2 q1 = *(const ulonglong2*)(s_h0w + 4);
                        ulonglong2 q2 = *(const ulonglong2*)(s_h0w + 8);
                        ulonglong2 q3 = *(const ulonglong2*)(s_h0w + 12);
                        H0c[0]=q0.x; H0c[1]=q0.y; H0c[2]=q1.x; H0c[3]=q1.y;
                        H0c[4]=q2.x; H0c[5]=q2.y; H0c[6]=q3.x; H0c[7]=q3.y;
                    }
                    if (lane < 16) s_h0r[t][lane] = h0own;
                }
#pragma unroll
                for (int k = 0; k < MCHUNK; k++) { xcS[k] = xnS[k]; xcN[k] = xnN[k]; }
            }
            __syncthreads();
        }
    } else if (wid == 1) {
        // ---- W1: xw1 projection ----
        u64 wiS1[8], wiN1[8];
        {
            const u64* pp;
            pp = (const u64*)(Wih1 + rowS * 16);
#pragma unroll
            for (int k = 0; k < 8; k++) wiS1[k] = pp[k];
            pp = (const u64*)(Wih1 + rowN * 16);
#pragma unroll
            for (int k = 0; k < 8; k++) wiN1[k] = pp[k];
        }
        const u64 biS1_2 = pack2(bih1[rowS], 0.f);
        const u64 biN1_2 = pack2(bih1[rowN], 0.f);

        for (int it = 0; it < MNCH + 2; it++) {
            if (it >= 1 && it <= MNCH) {
                const int c = it - 1;
#pragma unroll
                for (int k = 0; k < MCHUNK; k++) {
                    const int t = c * MCHUNK + k;
                    u64 H0[8];
                    {
                        ulonglong2 q0 = *(const ulonglong2*)(s_h0r[t]);
                        ulonglong2 q1 = *(const ulonglong2*)(s_h0r[t] + 4);
                        ulonglong2 q2 = *(const ulonglong2*)(s_h0r[t] + 8);
                        ulonglong2 q3 = *(const ulonglong2*)(s_h0r[t] + 12);
                        H0[0]=q0.x; H0[1]=q0.y; H0[2]=q1.x; H0[3]=q1.y;
                        H0[4]=q2.x; H0[5]=q2.y; H0[6]=q3.x; H0[7]=q3.y;
                    }
                    float xwS1 = dotp8b(wiS1, H0, biS1_2, Z2);
                    float xwN1 = dotp8b(wiN1, H0, biN1_2, Z2);
                    s_xw[t][lane] = xwS1;
                    if (lane < 16) s_xw[t][32 + lane] = xwN1;
                }
            }
            __syncthreads();
        }
    } else {
        // ---- W2: layer-1 ----
        u64 uS1[8], uN1[8];
        {
            const u64* pp;
            pp = (const u64*)(Whh1 + rowS * 16);
#pragma unroll
            for (int k = 0; k < 8; k++) uS1[k] = pp[k];
            pp = (const u64*)(Whh1 + rowN * 16);
#pragma unroll
            for (int k = 0; k < 8; k++) uN1[k] = pp[k];
        }
        const u64 bhS1_2 = pack2(bhh1[rowS], 0.f);
        const u64 bhN1_2 = pack2(bhh1[rowN], 0.f);

        s_h1w[lane] = 0.f;
        __syncwarp();
        float h1own = 0.f;

        u64 H1c[8];
#pragma unroll
        for (int k = 0; k < 8; k++) H1c[k] = Z2;

        for (int it = 0; it < MNCH + 2; it++) {
            if (it >= 2) {
                const int c = it - 2;
#pragma unroll
                for (int k = 0; k < MCHUNK; k++) {
                    const int t = c * MCHUNK + k;
                    float xwS1 = s_xw[t][lane];
                    float xwN1 = s_xw[t][32 + (lane & 15)];
                    float ghS1 = dotp8b(uS1, H1c, bhS1_2, Z2);
                    float ghN1 = dotp8b(uN1, H1c, bhN1_2, Z2);
                    float s1  = sigm_a(xwS1 + ghS1);
                    float nv1 = tanh_a(fmaf(s1, ghN1, xwN1));
                    float z1  = __shfl_sync(FULLMASK, s1, 16 + (lane & 15));
                    h1own = fmaf(z1, h1own - nv1, nv1);
                    s_h1w[lane] = h1own;
                    __syncwarp();
                    {
                        ulonglong2 r0 = *(const ulonglong2*)(s_h1w);
                        ulonglong2 r1 = *(const ulonglong2*)(s_h1w + 4);
                        ulonglong2 r2 = *(const ulonglong2*)(s_h1w + 8);
                        ulonglong2 r3 = *(const ulonglong2*)(s_h1w + 12);
                        H1c[0]=r0.x; H1c[1]=r0.y; H1c[2]=r1.x; H1c[3]=r1.y;
                        H1c[4]=r2.x; H1c[5]=r2.y; H1c[6]=r3.x; H1c[7]=r3.y;
                    }
                }
            }
            __syncthreads();
        }
        if (lane < 16) g_h1fin[b * 16 + lane] = h1own;
    }
}

// ============================================================================
// K4 (NEW, merged dec1+dec2): 16 blocks x 512 threads. Each block redundantly
// computes decoder layer-1 + BN + elu (arithmetic identical to old dec1),
// then its 4-batch output slice (identical to old dec2).
// ============================================================================
#define DEC_SMEM_BYTES ((16384 + 1024 + 2176 + 128 + 1024 + 512 + 32 + 32) * 4)
__global__ void __launch_bounds__(512) k_dec(
    const float* __restrict__ Remote,
    const float* __restrict__ w1, const float* __restrict__ b1,
    const float* __restrict__ gg, const float* __restrict__ bt,
    const float* __restrict__ w2, const float* __restrict__ b2,
    float* __restrict__ out)
{
    extern __shared__ float sm[];
    float* sw2   = sm;                  // 16384
    float* sb2   = sw2 + 16384;         // 1024
    float* sw1   = sb2 + 1024;          // 2176
    float* sb1   = sw1 + 2176;          // 128
    float* sh    = sb1 + 128;           // 1024
    float* sro   = sh  + 1024;          // 512
    float* sstat = sro + 512;           // 32
    float* sgb   = sstat + 32;          // 32

    const int tid = threadIdx.x;
    {
        const float4* w24 = (const float4*)w2;
        float4* sw24 = (float4*)sw2;
        for (int i = tid; i < 4096; i += 512) sw24[i] = w24[i];
        for (int i = tid; i < 1024; i += 512) sb2[i] = b2[i];
        for (int i = tid; i < 2176; i += 512) sw1[i] = w1[i];
        if (tid < 128) sb1[tid] = b1[tid];
        if (tid < 16) { sgb[tid] = gg[tid]; sgb[16 + tid] = bt[tid]; }
    }
    __syncthreads();

    // ---- decoder layer-1 (identical math to old k_dec1) ----
#pragma unroll
    for (int rr = 0; rr < 2; rr++) {
        const int idx = tid + rr * 512;
        const int b = idx >> 4, hh = idx & 15;
        float d[17];
#pragma unroll
        for (int k = 0; k < 16; k++) d[k] = g_h1fin[b * 16 + k];
        d[16] = Remote[((size_t)b * Wn + (Wn - 1)) * Fn + (An + TGTn)];
        float acc = 0.f;
#pragma unroll 1
        for (int e = 0; e < 8; e++) {
            float ro = g_Ro[((size_t)b * Wn + (Wn - 1)) * En + e];
            float pe = sb1[e * 16 + hh];
#pragma unroll
            for (int i = 0; i < 17; i++) pe = fmaf(d[i], sw1[e * 272 + i * 16 + hh], pe);
            acc = fmaf(ro, pe, acc);
        }
        sh[idx] = acc;
        if (hh < 8) sro[b * 8 + hh] = g_Ro[((size_t)b * Wn + (Wn - 1)) * En + hh];
    }
    __syncthreads();
    if (tid < 16) {
        float s = 0.f, q = 0.f;
        for (int bb = 0; bb < 64; bb++) {
            float v = sh[bb * 16 + tid];
            s += v; q = fmaf(v, v, q);
        }
        float mean = s * (1.0f / 64.0f);
        float var  = q * (1.0f / 64.0f) - mean * mean;
        sstat[tid] = mean;
        sstat[16 + tid] = rsqrtf(var + 1e-5f);
    }
    __syncthreads();
#pragma unroll
    for (int rr = 0; rr < 2; rr++) {
        const int idx = tid + rr * 512;
        const int hh = idx & 15;
        float v = sh[idx];
        v = fmaf(sgb[hh] * (v - sstat[hh]), sstat[16 + hh], sgb[16 + hh]);
        __syncthreads();
        sh[idx] = (v > 0.f) ? v : (__expf(v) - 1.0f);
    }
    __syncthreads();

    // ---- decoder layer-2 (identical math to old k_dec2) ----
    const int b = blockIdx.x * 4 + (tid >> 7);
    const int o = tid & 127;

    float dh[16];
    const float4* hp = (const float4*)(sh + b * 16);
#pragma unroll
    for (int q4 = 0; q4 < 4; q4++) {
        float4 v = hp[q4];
        dh[q4*4+0]=v.x; dh[q4*4+1]=v.y; dh[q4*4+2]=v.z; dh[q4*4+3]=v.w;
    }
    float ro[8];
#pragma unroll
    for (int e = 0; e < 8; e++) ro[e] = sro[b * 8 + e];

    float acc = 0.f;
#pragma unroll 1
    for (int e = 0; e < 8; e++) {
        float pe = sb2[e * 128 + o];
        const float* wrow = sw2 + e * 2048 + o;
#pragma unroll
        for (int h = 0; h < 16; h++) pe = fmaf(dh[h], wrow[h * 128], pe);
        acc = fmaf(ro[e], pe, acc);
    }
    out[b * 128 + o] = acc;
}

// ============================================================================
// Host launcher
// ============================================================================
extern "C" void kernel_launch(void* const* d_in, const int* in_sizes, int n_in,
                              void* d_out, int out_size)
{
    (void)n_in; (void)out_size;
    const float* P[30];
    for (int i = 0; i < 30; i++) P[i] = (const float*)d_in[i];

    const float *Local = P[0], *Remote = P[1];
    const float *gWih0 = P[2], *gWhh0 = P[3], *gbih0 = P[4], *gbhh0 = P[5];
    const float *gWih1 = P[6], *gWhh1 = P[7], *gbih1 = P[8], *gbhh1 = P[9];
    const float *aew1, *aeb1, *aew2, *aeb2, *aeg, *aebt;
    const float *mdw1, *mdb1, *mdw2, *mdb2, *mdg, *mdbt;
    const float *mWih0, *mWhh0, *mbih0, *mbhh0, *mWih1, *mWhh1, *mbih1, *mbhh1;

    if (in_sizes[10] == 16384) {   // reference-signature order
        aew1 = P[10]; aeb1 = P[11]; aew2 = P[12]; aeb2 = P[13]; aeg = P[14]; aebt = P[15];
        mdw1 = P[16]; mdb1 = P[17]; mdw2 = P[18]; mdb2 = P[19]; mdg = P[20]; mdbt = P[21];
        mWih0 = P[22]; mWhh0 = P[23]; mbih0 = P[24]; mbhh0 = P[25];
        mWih1 = P[26]; mWhh1 = P[27]; mbih1 = P[28]; mbhh1 = P[29];
    } else {                        // setup_inputs dict order
        mWih0 = P[10]; mWhh0 = P[11]; mbih0 = P[12]; mbhh0 = P[13];
        mWih1 = P[14]; mWhh1 = P[15]; mbih1 = P[16]; mbhh1 = P[17];
        aew1 = P[18]; aeb1 = P[19]; aew2 = P[20]; aeb2 = P[21]; aeg = P[22]; aebt = P[23];
        mdw1 = P[24]; mdb1 = P[25]; mdw2 = P[26]; mdb2 = P[27]; mdg = P[28]; mdbt = P[29];
    }

    cudaFuncSetAttribute(k_dec, cudaFuncAttributeMaxDynamicSharedMemorySize, DEC_SMEM_BYTES);

    k_ge1<<<384, 256, GE1_SMEM_BYTES>>>(Local, Remote,
                                        gWih0, gWhh0, gbih0, gbhh0,
                                        gWih1, gWhh1, gbih1, gbhh1,
                                        aew1, aeb1);
    k_cexp2<<<256, 256>>>(aew2, aeb2, aeg, aebt, mWih0, mbih0);
    k_mixer<<<64, 96>>>(mWhh0, mbhh0, mWih1, mbih1, mWhh1, mbhh1);
    k_dec<<<16, 512, DEC_SMEM_BYTES>>>(Remote, mdw1, mdb1, mdg, mdbt,
                                       mdw2, mdb2, (float*)d_out);
}

// round 15
// speedup vs baseline: 1.1222x; 1.1222x over previous
#include <cuda_runtime.h>
#include <math.h>

#define FULLMASK 0xffffffffu
#define Bn   64
#define Wn   128
#define Fn   132
#define An   128
#define TGTn 3
#define En   8
#define HIDn 16
#define OUTn 128
#define NROW (Bn*Wn)

typedef unsigned long long u64;

// ---------------- scratch (device globals; no allocation) ----------------
__device__ float g_Lo[NROW*En];
__device__ float g_Ro[NROW*En];
__device__ float g_y[2*NROW*128];
__device__ float g_part2[2][256][2][16];
__device__ unsigned g_bar;            // monotonic epoch counter (zero-init)
__device__ float g_xw0[NROW*48];
__device__ float g_h1fin[Bn*HIDn];

// HW-approx activations
__device__ __forceinline__ float tanh_a(float x) {
    float y; asm("tanh.approx.f32 %0, %1;" : "=f"(y) : "f"(x)); return y;
}
__device__ __forceinline__ float sigm_a(float x) { return fmaf(0.5f, tanh_a(0.5f * x), 0.5f); }
__device__ __forceinline__ float ex2_a(float x) {
    float y; asm("ex2.approx.f32 %0, %1;" : "=f"(y) : "f"(x)); return y;
}

// packed f32x2 helpers
__device__ __forceinline__ u64 pack2(float lo, float hi) {
    u64 r; asm("mov.b64 %0, {%1,%2};" : "=l"(r) : "f"(lo), "f"(hi)); return r;
}
__device__ __forceinline__ void unpack2(u64 v, float& lo, float& hi) {
    asm("mov.b64 {%0,%1}, %2;" : "=f"(lo), "=f"(hi) : "l"(v));
}
__device__ __forceinline__ u64 ffma2(u64 a, u64 b, u64 c) {
    u64 d; asm("fma.rn.f32x2 %0, %1, %2, %3;" : "=l"(d) : "l"(a), "l"(b), "l"(c)); return d;
}

__device__ __forceinline__ float dotp8b(const u64* w, const u64* h, u64 bias2, u64 zero2) {
    u64 a = ffma2(w[0], h[0], bias2);
    u64 b = ffma2(w[1], h[1], zero2);
    a = ffma2(w[2], h[2], a); b = ffma2(w[3], h[3], b);
    a = ffma2(w[4], h[4], a); b = ffma2(w[5], h[5], b);
    a = ffma2(w[6], h[6], a); b = ffma2(w[7], h[7], b);
    float al, ah, bl, bh;
    unpack2(a, al, ah); unpack2(b, bl, bh);
    return (al + ah) + (bl + bh);
}

__device__ __forceinline__ float dotp4b(const u64* w, const u64* h, u64 bias2, u64 zero2) {
    u64 a = ffma2(w[0], h[0], bias2);
    u64 b = ffma2(w[1], h[1], zero2);
    a = ffma2(w[2], h[2], a);
    b = ffma2(w[3], h[3], b);
    float al, ah, bl, bh;
    unpack2(a, al, ah); unpack2(b, bl, bh);
    return (al + ah) + (bl + bh);
}

#define GCHUNK 8
#define GNCH   (Wn / GCHUNK)

// ============================================================================
// K1 fused (verbatim): blocks 0..127 gate GRU v3 (2-warp); 128..383 GEMM.
// ============================================================================
#define GE1_SMEM_BYTES ((64*129 + 128) * 4)
__global__ void __launch_bounds__(256) k_ge1(
    const float* __restrict__ Local, const float* __restrict__ Remote,
    const float* __restrict__ Wih0, const float* __restrict__ Whh0,
    const float* __restrict__ bih0, const float* __restrict__ bhh0,
    const float* __restrict__ Wih1, const float* __restrict__ Whh1,
    const float* __restrict__ bih1, const float* __restrict__ bhh1,
    const float* __restrict__ w1,   const float* __restrict__ b1)
{
    extern __shared__ float smdyn[];

    if (blockIdx.x < 128) {
        if (threadIdx.x >= 64) return;
        __shared__ __align__(16) float sh0[8];
        __shared__ __align__(16) float sh1[8];
        float* sring = smdyn;

        const int tid  = threadIdx.x;
        const int wid  = tid >> 5;
        const int lane = tid & 31;
        const int side = blockIdx.x >> 6;
        const int b    = blockIdx.x & 63;
        const float* in  = side ? Remote : Local;
        float*       out = side ? g_Ro   : g_Lo;

        const int j    = lane & 7;
        const bool isZ = (lane >= 8)  && (lane < 16);
        const bool isN = (lane >= 16) && (lane < 24);
        const int rowA = (isZ || isN) ? lane : 0;
        const int rowB = j;
        const float scA = isZ ? 0.5f : 1.0f;
        const u64 Z2 = pack2(0.f, 0.f);

        if (wid == 0) {
            u64 uA0p[4], uB0p[4], wiA1p[4], wiB1p[4];
            float wxA[3], wxB[3];
            u64 bA0_2, bB0_2, biA1_2, biB1_2;
            float biA0 = 0.f, biB0 = 0.f;
            {
                float tA[8], tB[8];
#pragma unroll
                for (int k = 0; k < 8; k++) {
                    tA[k] = (isZ || isN) ? scA * Whh0[rowA*8+k] : 0.f;
                    tB[k] = isN ? 0.5f * Whh0[rowB*8+k] : 0.f;
                }
#pragma unroll
                for (int k = 0; k < 4; k++) {
                    uA0p[k] = pack2(tA[2*k], tA[2*k+1]);
                    uB0p[k] = pack2(tB[2*k], tB[2*k+1]);
                }
#pragma unroll
                for (int k = 0; k < 8; k++) {
                    tA[k] = (isZ || isN) ? scA * Wih1[rowA*8+k] : 0.f;
                    tB[k] = isN ? 0.5f * Wih1[rowB*8+k] : 0.f;
                }
#pragma unroll
                for (int k = 0; k < 4; k++) {
                    wiA1p[k] = pack2(tA[2*k], tA[2*k+1]);
                    wiB1p[k] = pack2(tB[2*k], tB[2*k+1]);
                }
#pragma unroll
                for (int c = 0; c < 3; c++) {
                    wxA[c] = (isZ || isN) ? scA * Wih0[rowA*3+c] : 0.f;
                    wxB[c] = isN ? 0.5f * Wih0[rowB*3+c] : 0.f;
                }
                biA0 = (isZ || isN) ? scA * bih0[rowA] : 0.f;
                biB0 = isN ? 0.5f * bih0[rowB] : 0.f;
                bA0_2 = pack2((isZ || isN) ? scA * bhh0[rowA] : 0.f, 0.f);
                bB0_2 = pack2(isN ? 0.5f * bhh0[rowB] : 0.f, 0.f);
                biA1_2 = pack2((isZ || isN) ? scA * bih1[rowA] : 0.f, 0.f);
                biB1_2 = pack2(isN ? 0.5f * bih1[rowB] : 0.f, 0.f);
            }

            if (isZ) sh0[j] = 0.f;
            __syncwarp();
            float h0own = 0.f;

            u64 H0c[4];
            {
                ulonglong2 q0 = *(const ulonglong2*)(sh0);
                ulonglong2 q1 = *(const ulonglong2*)(sh0 + 4);
                H0c[0]=q0.x; H0c[1]=q0.y; H0c[2]=q1.x; H0c[3]=q1.y;
            }

            const float* px = in + (size_t)b * Wn * Fn + An;
            float xc0[GCHUNK], xc1[GCHUNK], xc2[GCHUNK];
            float xn0[GCHUNK], xn1[GCHUNK], xn2[GCHUNK];
#pragma unroll
            for (int k = 0; k < GCHUNK; k++) {
                const float* p = px + (size_t)k * Fn;
                xc0[k] = p[0]; xc1[k] = p[1]; xc2[k] = p[2];
            }

            for (int c = 0; c < GNCH; c++) {
                {
                    int base = ((c + 1) & (GNCH - 1)) * GCHUNK;
#pragma unroll
                    for (int k = 0; k < GCHUNK; k++) {
                        const float* p = px + (size_t)(base + k) * Fn;
                        xn0[k] = p[0]; xn1[k] = p[1]; xn2[k] = p[2];
                    }
                }
#pragma unroll
                for (int k = 0; k < GCHUNK; k++) {
                    const int t = c * GCHUNK + k;
                    float ghA = dotp4b(uA0p, H0c, bA0_2, Z2);
                    float ghB = dotp4b(uB0p, H0c, bB0_2, Z2);
                    float xwA = fmaf(wxA[0], xc0[k], fmaf(wxA[1], xc1[k], fmaf(wxA[2], xc2[k], biA0)));
                    float xwB = fmaf(wxB[0], xc0[k], fmaf(wxB[1], xc1[k], fmaf(wxB[2], xc2[k], biB0)));
                    float preS = isN ? (xwB + ghB) : (xwA + ghA);
                    float s = fmaf(0.5f, tanh_a(preS), 0.5f);
                    float nv = tanh_a(fmaf(s, ghA, xwA));
                    float nvz = __shfl_sync(FULLMASK, nv, lane + 8);
                    if (isZ) {
                        h0own = fmaf(s, h0own - nvz, nvz);
                        sh0[j] = h0own;
                    }
                    __syncwarp();
                    {
                        ulonglong2 q0 = *(const ulonglong2*)(sh0);
                        ulonglong2 q1 = *(const ulonglong2*)(sh0 + 4);
                        H0c[0]=q0.x; H0c[1]=q0.y; H0c[2]=q1.x; H0c[3]=q1.y;
                    }
                    float xwA1 = dotp4b(wiA1p, H0c, biA1_2, Z2);
                    float xwB1 = dotp4b(wiB1p, H0c, biB1_2, Z2);
                    sring[t * 64 + lane] = xwA1;
                    if (isN) sring[t * 64 + 32 + j] = xwB1;
                }
#pragma unroll
                for (int k = 0; k < GCHUNK; k++) { xc0[k]=xn0[k]; xc1[k]=xn1[k]; xc2[k]=xn2[k]; }
                __syncthreads();
            }
        } else {
            u64 uA1p[4], uB1p[4];
            u64 bhA1_2, bhB1_2;
            {
                float tA[8], tB[8];
#pragma unroll
                for (int k = 0; k < 8; k++) {
                    tA[k] = (isZ || isN) ? scA * Whh1[rowA*8+k] : 0.f;
                    tB[k] = isN ? 0.5f * Whh1[rowB*8+k] : 0.f;
                }
#pragma unroll
                for (int k = 0; k < 4; k++) {
                    uA1p[k] = pack2(tA[2*k], tA[2*k+1]);
                    uB1p[k] = pack2(tB[2*k], tB[2*k+1]);
                }
                bhA1_2 = pack2((isZ || isN) ? scA * bhh1[rowA] : 0.f, 0.f);
                bhB1_2 = pack2(isN ? 0.5f * bhh1[rowB] : 0.f, 0.f);
            }

            if (isZ) sh1[j] = 0.f;
            __syncwarp();
            float h1own = 0.f;

            u64 H1c[4];
            {
                ulonglong2 r0 = *(const ulonglong2*)(sh1);
                ulonglong2 r1 = *(const ulonglong2*)(sh1 + 4);
                H1c[0]=r0.x; H1c[1]=r0.y; H1c[2]=r1.x; H1c[3]=r1.y;
            }

            for (int c = 0; c < GNCH; c++) {
                __syncthreads();
#pragma unroll
                for (int k = 0; k < GCHUNK; k++) {
                    const int t = c * GCHUNK + k;
                    float xwA1 = sring[t * 64 + lane];
                    float xwB1 = sring[t * 64 + 32 + j];
                    float ghA1 = dotp4b(uA1p, H1c, bhA1_2, Z2);
                    float ghB1 = dotp4b(uB1p, H1c, bhB1_2, Z2);
                    float preS1 = isN ? (xwB1 + ghB1) : (xwA1 + ghA1);
                    float s1 = fmaf(0.5f, tanh_a(preS1), 0.5f);
                    float nv1 = tanh_a(fmaf(s1, ghA1, xwA1));
                    float nvz1 = __shfl_sync(FULLMASK, nv1, lane + 8);
                    if (isZ) {
                        h1own = fmaf(s1, h1own - nvz1, nvz1);
                        sh1[j] = h1own;
                    }
                    __syncwarp();
                    {
                        ulonglong2 r0 = *(const ulonglong2*)(sh1);
                        ulonglong2 r1 = *(const ulonglong2*)(sh1 + 4);
                        H1c[0]=r0.x; H1c[1]=r0.y; H1c[2]=r1.x; H1c[3]=r1.y;
                    }
                    float myh = sh1[j];
                    float ex = ex2_a(myh * 1.44269504f);
                    float ssum = ex;
                    ssum += __shfl_xor_sync(FULLMASK, ssum, 1);
                    ssum += __shfl_xor_sync(FULLMASK, ssum, 2);
                    ssum += __shfl_xor_sync(FULLMASK, ssum, 4);
                    if (lane < 8)
                        out[((size_t)b * Wn + t) * En + lane] = ex * __frcp_rn(ssum);
                }
            }
        }
        return;
    }

    // ---------------- per-expert GEMM path (verbatim) ----------------
    float* sx  = smdyn;
    float* sb1 = sx + 64 * 129;

    const int gid  = blockIdx.x - 128;
    const int side = gid >> 7;
    const int tile = gid & 127;
    const int n0   = tile * 64;
    const float* in = side ? Remote : Local;
    const int tid   = threadIdx.x;

    for (int i = tid; i < 64 * 128; i += 256) {
        int r = i >> 7, c = i & 127;
        sx[r * 129 + c] = in[(size_t)(n0 + r) * Fn + c];
    }
    if (tid < 128) sb1[tid] = b1[tid];
    __syncthreads();

    const int rg = tid >> 4, cg = tid & 15;
    const int r0 = rg * 4, c0 = cg * 8;
    const int e  = c0 >> 4, hb = c0 & 15;
    const float* wbase = w1 + e * 2048 + hb;

    u64 acc[4][4];
    {
        u64 i0 = pack2(sb1[c0+0], sb1[c0+1]);
        u64 i1 = pack2(sb1[c0+2], sb1[c0+3]);
        u64 i2 = pack2(sb1[c0+4], sb1[c0+5]);
        u64 i3 = pack2(sb1[c0+6], sb1[c0+7]);
#pragma unroll
        for (int jj = 0; jj < 4; jj++) { acc[jj][0]=i0; acc[jj][1]=i1; acc[jj][2]=i2; acc[jj][3]=i3; }
    }

#pragma unroll 2
    for (int k = 0; k < 128; k++) {
        float xv0 = sx[(r0+0)*129 + k];
        float xv1 = sx[(r0+1)*129 + k];
        float xv2 = sx[(r0+2)*129 + k];
        float xv3 = sx[(r0+3)*129 + k];
        ulonglong2 wA = *(const ulonglong2*)(wbase + k*16);
        ulonglong2 wB = *(const ulonglong2*)(wbase + k*16 + 4);
        u64 x0 = pack2(xv0, xv0), x1 = pack2(xv1, xv1);
        u64 x2 = pack2(xv2, xv2), x3 = pack2(xv3, xv3);
        acc[0][0]=ffma2(x0,wA.x,acc[0][0]); acc[0][1]=ffma2(x0,wA.y,acc[0][1]);
        acc[0][2]=ffma2(x0,wB.x,acc[0][2]); acc[0][3]=ffma2(x0,wB.y,acc[0][3]);
        acc[1][0]=ffma2(x1,wA.x,acc[1][0]); acc[1][1]=ffma2(x1,wA.y,acc[1][1]);
        acc[1][2]=ffma2(x1,wB.x,acc[1][2]); acc[1][3]=ffma2(x1,wB.y,acc[1][3]);
        acc[2][0]=ffma2(x2,wA.x,acc[2][0]); acc[2][1]=ffma2(x2,wA.y,acc[2][1]);
        acc[2][2]=ffma2(x2,wB.x,acc[2][2]); acc[2][3]=ffma2(x2,wB.y,acc[2][3]);
        acc[3][0]=ffma2(x3,wA.x,acc[3][0]); acc[3][1]=ffma2(x3,wA.y,acc[3][1]);
        acc[3][2]=ffma2(x3,wB.x,acc[3][2]); acc[3][3]=ffma2(x3,wB.y,acc[3][3]);
    }

#pragma unroll
    for (int jj = 0; jj < 4; jj++) {
        float* yrow = g_y + ((size_t)side * NROW + n0 + r0 + jj) * 128 + c0;
        ulonglong2 v0; v0.x = acc[jj][0]; v0.y = acc[jj][1];
        ulonglong2 v1; v1.x = acc[jj][2]; v1.y = acc[jj][3];
        *(ulonglong2*)(yrow)     = v0;
        *(ulonglong2*)(yrow + 4) = v1;
    }
}

// ============================================================================
// K2 (merged comb+exp2, reduce v2): per-block h, BN partials, grid barrier,
// fast deterministic partial-reduce (256 threads, unroll 8, fixed 4-way
// combine), then BN+elu / layer-2 GEMM / mixer projection.
// ============================================================================
__global__ void __launch_bounds__(256, 2) k_cexp2(
    const float* __restrict__ w2, const float* __restrict__ b2,
    const float* __restrict__ aeg, const float* __restrict__ aebt,
    const float* __restrict__ Wih0m, const float* __restrict__ bih0m)
{
    __shared__ float sW2T[16*132];
    __shared__ float sb2[128];
    __shared__ float sWp[768];
    __shared__ float sbi[48];
    __shared__ float sg[16], sbt[16];
    __shared__ float sstat[64];
    __shared__ float su[32*136];
    __shared__ float sz[32*20];
    __shared__ float s_hL[32][16];
    __shared__ float s_hR[32][16];
    __shared__ float s_red4[4][64];

    const int tid = threadIdx.x;
    const int bx  = blockIdx.x;
    const int n0  = bx * 32;

    for (int i = tid; i < 2048; i += 256) {
        int ii = i >> 4, o = i & 15;
        sW2T[o * 132 + ii] = w2[i];
    }
    for (int i = tid; i < 768; i += 256) sWp[i] = Wih0m[i];
    if (tid < 128) sb2[tid] = b2[tid];
    if (tid < 48)  sbi[tid] = bih0m[tid];
    if (tid < 16)  { sg[tid] = aeg[tid]; sbt[tid] = aebt[tid]; }

    const int r   = tid >> 3;      // 0..31
    const int p   = tid & 7;
    const int h0i = 2 * p;
    const int n   = n0 + r;

    // ---- phase 0: h for our rows ----
    float oL[8], oR[8];
    {
        float4 a = *(const float4*)(g_Lo + (size_t)n * 8);
        float4 b = *(const float4*)(g_Lo + (size_t)n * 8 + 4);
        oL[0]=a.x; oL[1]=a.y; oL[2]=a.z; oL[3]=a.w; oL[4]=b.x; oL[5]=b.y; oL[6]=b.z; oL[7]=b.w;
        float4 c = *(const float4*)(g_Ro + (size_t)n * 8);
        float4 d = *(const float4*)(g_Ro + (size_t)n * 8 + 4);
        oR[0]=c.x; oR[1]=c.y; oR[2]=c.z; oR[3]=c.w; oR[4]=d.x; oR[5]=d.y; oR[6]=d.z; oR[7]=d.w;
    }
    {
        const float* yL = g_y + (size_t)n * 128;
        const float* yR = g_y + ((size_t)NROW + n) * 128;
        float aL0=0.f, aL1=0.f, aR0=0.f, aR1=0.f;
#pragma unroll
        for (int e = 0; e < 8; e++) {
            float2 vL = *(const float2*)(yL + e*16 + h0i);
            float2 vR = *(const float2*)(yR + e*16 + h0i);
            aL0 = fmaf(oL[e], vL.x, aL0); aL1 = fmaf(oL[e], vL.y, aL1);
            aR0 = fmaf(oR[e], vR.x, aR0); aR1 = fmaf(oR[e], vR.y, aR1);
        }
        s_hL[r][h0i] = aL0; s_hL[r][h0i+1] = aL1;
        s_hR[r][h0i] = aR0; s_hR[r][h0i+1] = aR1;
    }
    __syncthreads();

    // ---- block BN partials (deterministic serial over 32 rows) ----
    if (tid < 64) {
        int side = tid >> 5, h = (tid >> 1) & 15, w = tid & 1;
        const float (*sh_)[16] = side ? s_hR : s_hL;
        float a = 0.f;
#pragma unroll 4
        for (int rr = 0; rr < 32; rr++) {
            float v = sh_[rr][h];
            a = w ? fmaf(v, v, a) : (a + v);
        }
        g_part2[side][bx][w][h] = a;
    }
    __threadfence();
    __syncthreads();

    // ---- grid spin-barrier (ticketed epoch) ----
    if (tid == 0) {
        unsigned t = atomicAdd(&g_bar, 1u);
        unsigned target = (t / 256u) * 256u + 256u;
        while (*(volatile unsigned*)&g_bar < target) { }
    }
    __syncthreads();
    __threadfence();

    // ---- reduce partials: 4 groups x 64 stats, unroll 8, fixed combine ----
    {
        const int q = tid >> 6, s = tid & 63;
        const int side = s >> 5, h = (s >> 1) & 15, w = s & 1;
        float a = 0.f;
        const int c0q = q * 64;
#pragma unroll 8
        for (int c = 0; c < 64; c++) a += g_part2[side][c0q + c][w][h];
        s_red4[q][s] = a;
    }
    __syncthreads();
    if (tid < 32) {
        int side = tid >> 4, h = tid & 15;
        const int sS = side * 32 + h * 2 + 0;
        const int sQ = side * 32 + h * 2 + 1;
        float s = (s_red4[0][sS] + s_red4[1][sS]) + (s_red4[2][sS] + s_red4[3][sS]);
        float q = (s_red4[0][sQ] + s_red4[1][sQ]) + (s_red4[2][sQ] + s_red4[3][sQ]);
        float mean = s * (1.0f / NROW);
        float var  = q * (1.0f / NROW) - mean * mean;
        sstat[side * 32 + h]      = mean;
        sstat[side * 32 + 16 + h] = rsqrtf(var + 1e-5f);
    }
    __syncthreads();

    {   // phase A: build u (h from smem)
        float hlx = s_hL[r][h0i], hly = s_hL[r][h0i+1];
        float hrx = s_hR[r][h0i], hry = s_hR[r][h0i+1];
        float vL0 = fmaf(sg[h0i]   * (hlx - sstat[h0i]),        sstat[16+h0i],   sbt[h0i]);
        float vL1 = fmaf(sg[h0i+1] * (hly - sstat[h0i+1]),      sstat[16+h0i+1], sbt[h0i+1]);
        float vR0 = fmaf(sg[h0i]   * (hrx - sstat[32+h0i]),     sstat[48+h0i],   sbt[h0i]);
        float vR1 = fmaf(sg[h0i+1] * (hry - sstat[32+h0i+1]),   sstat[48+h0i+1], sbt[h0i+1]);
        vL0 = (vL0 > 0.f) ? vL0 : (__expf(vL0) - 1.0f);
        vL1 = (vL1 > 0.f) ? vL1 : (__expf(vL1) - 1.0f);
        vR0 = (vR0 > 0.f) ? vR0 : (__expf(vR0) - 1.0f);
        vR1 = (vR1 > 0.f) ? vR1 : (__expf(vR1) - 1.0f);
        float* ur = su + r * 136;
#pragma unroll
        for (int e = 0; e < 8; e++) {
            ur[e*16 + h0i]     = fmaf(oL[e], vL0, oR[e] * vR0);
            ur[e*16 + h0i + 1] = fmaf(oL[e], vL1, oR[e] * vR1);
        }
        if (p == 0) {
#pragma unroll
            for (int e = 0; e < 8; e++) ur[128 + e] = oL[e] + oR[e];
        }
    }
    __syncthreads();

    {   // phase B
        const int g2 = tid >> 4, o = tid & 15;
        const int ra = 2 * g2, rb = ra + 1;
        float acc0 = 0.f, acc1 = 0.f;
        const float* osA = su + ra * 136 + 128;
        const float* osB = su + rb * 136 + 128;
#pragma unroll
        for (int e = 0; e < 8; e++) {
            float w = sb2[e * 16 + o];
            acc0 = fmaf(osA[e], w, acc0);
            acc1 = fmaf(osB[e], w, acc1);
        }
        const float* wrow = sW2T + o * 132;
        const float* uA = su + ra * 136;
        const float* uB = su + rb * 136;
#pragma unroll 4
        for (int i = 0; i < 128; i += 4) {
            float4 w = *(const float4*)(wrow + i);
            float4 a = *(const float4*)(uA + i);
            float4 b = *(const float4*)(uB + i);
            acc0 = fmaf(a.x, w.x, acc0); acc1 = fmaf(b.x, w.x, acc1);
            acc0 = fmaf(a.y, w.y, acc0); acc1 = fmaf(b.y, w.y, acc1);
            acc0 = fmaf(a.z, w.z, acc0); acc1 = fmaf(b.z, w.z, acc1);
            acc0 = fmaf(a.w, w.w, acc0); acc1 = fmaf(b.w, w.w, acc1);
        }
        sz[ra * 20 + o] = acc0;
        sz[rb * 20 + o] = acc1;
    }
    __syncthreads();

    {   // phase C
        const int sl = tid & 7;
        float zv[16];
        const float4* zp = (const float4*)(sz + r * 20);
#pragma unroll
        for (int q4 = 0; q4 < 4; q4++) {
            float4 v = zp[q4];
            zv[q4*4+0]=v.x; zv[q4*4+1]=v.y; zv[q4*4+2]=v.z; zv[q4*4+3]=v.w;
        }
        float* dst = g_xw0 + (size_t)n * 48 + sl * 6;
#pragma unroll
        for (int jo = 0; jo < 6; jo++) {
            int o = sl * 6 + jo;
            const float* wr = sWp + o * 16;
            float a = sbi[o], bsum = 0.f;
#pragma unroll
            for (int k = 0; k < 16; k += 2) {
                a    = fmaf(zv[k],   wr[k],   a);
                bsum = fmaf(zv[k+1], wr[k+1], bsum);
            }
            dst[jo] = a + bsum;
        }
    }
}

// ============================================================================
// K3 (verbatim R14): mixer GRU, THREE-warp pipeline.
// ============================================================================
#define MCHUNK 8
#define MNCH   (Wn / MCHUNK)
__global__ void __launch_bounds__(96) k_mixer(
    const float* __restrict__ Whh0, const float* __restrict__ bhh0,
    const float* __restrict__ Wih1, const float* __restrict__ bih1,
    const float* __restrict__ Whh1, const float* __restrict__ bhh1)
{
    __shared__ __align__(16) float s_h0w[32];
    __shared__ __align__(16) float s_h1w[32];
    __shared__ __align__(16) float s_h0r[Wn][16];
    __shared__ float s_xw[Wn][48];

    const int tid  = threadIdx.x;
    const int wid  = tid >> 5;
    const int lane = tid & 31;
    const int b    = blockIdx.x;
    const int rowS = lane;
    const int rowN = 32 + (lane & 15);
    const u64 Z2 = pack2(0.f, 0.f);

    if (wid == 0) {
        u64 uS0[8], uN0[8];
        {
            const u64* pp;
            pp = (const u64*)(Whh0 + rowS * 16);
#pragma unroll
            for (int k = 0; k < 8; k++) uS0[k] = pp[k];
            pp = (const u64*)(Whh0 + rowN * 16);
#pragma unroll
            for (int k = 0; k < 8; k++) uN0[k] = pp[k];
        }
        const u64 bS0_2 = pack2(bhh0[rowS], 0.f);
        const u64 bN0_2 = pack2(bhh0[rowN], 0.f);

        s_h0w[lane] = 0.f;
        __syncwarp();
        float h0own = 0.f;

        u64 H0c[8];
#pragma unroll
        for (int k = 0; k < 8; k++) H0c[k] = Z2;

        const float* xp = g_xw0 + (size_t)b * Wn * 48;
        float xcS[MCHUNK], xcN[MCHUNK], xnS[MCHUNK], xnN[MCHUNK];
#pragma unroll
        for (int k = 0; k < MCHUNK; k++) {
            xcS[k] = xp[(size_t)k * 48 + rowS];
            xcN[k] = xp[(size_t)k * 48 + rowN];
        }

        for (int it = 0; it < MNCH + 2; it++) {
            if (it < MNCH) {
                {
                    int base = ((it + 1) & (MNCH - 1)) * MCHUNK;
#pragma unroll
                    for (int k = 0; k < MCHUNK; k++) {
                        xnS[k] = xp[(size_t)(base + k) * 48 + rowS];
                        xnN[k] = xp[(size_t)(base + k) * 48 + rowN];
                    }
                }
#pragma unroll
                for (int k = 0; k < MCHUNK; k++) {
                    const int t = it * MCHUNK + k;
                    float ghS0 = dotp8b(uS0, H0c, bS0_2, Z2);
                    float ghN0 = dotp8b(uN0, H0c, bN0_2, Z2);
                    float s0  = sigm_a(xcS[k] + ghS0);
                    float nv0 = tanh_a(fmaf(s0, ghN0, xcN[k]));
                    float z0  = __shfl_sync(FULLMASK, s0, 16 + (lane & 15));
                    h0own = fmaf(z0, h0own - nv0, nv0);
                    s_h0w[lane] = h0own;
                    __syncwarp();
                    {
                        ulonglong2 q0 = *(const ulonglong2*)(s_h0w);
                        ulonglong2 q1 = *(const ulonglong2*)(s_h0w + 4);
                        ulonglong2 q2 = *(const ulonglong2*)(s_h0w + 8);
                        ulonglong2 q3 = *(const ulonglong2*)(s_h0w + 12);
                        H0c[0]=q0.x; H0c[1]=q0.y; H0c[2]=q1.x; H0c[3]=q1.y;
                        H0c[4]=q2.x; H0c[5]=q2.y; H0c[6]=q3.x; H0c[7]=q3.y;
                    }
                    if (lane < 16) s_h0r[t][lane] = h0own;
                }
#pragma unroll
                for (int k = 0; k < MCHUNK; k++) { xcS[k] = xnS[k]; xcN[k] = xnN[k]; }
            }
            __syncthreads();
        }
    } else if (wid == 1) {
        u64 wiS1[8], wiN1[8];
        {
            const u64* pp;
            pp = (const u64*)(Wih1 + rowS * 16);
#pragma unroll
            for (int k = 0; k < 8; k++) wiS1[k] = pp[k];
            pp = (const u64*)(Wih1 + rowN * 16);
#pragma unroll
            for (int k = 0; k < 8; k++) wiN1[k] = pp[k];
        }
        const u64 biS1_2 = pack2(bih1[rowS], 0.f);
        const u64 biN1_2 = pack2(bih1[rowN], 0.f);

        for (int it = 0; it < MNCH + 2; it++) {
            if (it >= 1 && it <= MNCH) {
                const int c = it - 1;
#pragma unroll
                for (int k = 0; k < MCHUNK; k++) {
                    const int t = c * MCHUNK + k;
                    u64 H0[8];
                    {
                        ulonglong2 q0 = *(const ulonglong2*)(s_h0r[t]);
                        ulonglong2 q1 = *(const ulonglong2*)(s_h0r[t] + 4);
                        ulonglong2 q2 = *(const ulonglong2*)(s_h0r[t] + 8);
                        ulonglong2 q3 = *(const ulonglong2*)(s_h0r[t] + 12);
                        H0[0]=q0.x; H0[1]=q0.y; H0[2]=q1.x; H0[3]=q1.y;
                        H0[4]=q2.x; H0[5]=q2.y; H0[6]=q3.x; H0[7]=q3.y;
                    }
                    float xwS1 = dotp8b(wiS1, H0, biS1_2, Z2);
                    float xwN1 = dotp8b(wiN1, H0, biN1_2, Z2);
                    s_xw[t][lane] = xwS1;
                    if (lane < 16) s_xw[t][32 + lane] = xwN1;
                }
            }
            __syncthreads();
        }
    } else {
        u64 uS1[8], uN1[8];
        {
            const u64* pp;
            pp = (const u64*)(Whh1 + rowS * 16);
#pragma unroll
            for (int k = 0; k < 8; k++) uS1[k] = pp[k];
            pp = (const u64*)(Whh1 + rowN * 16);
#pragma unroll
            for (int k = 0; k < 8; k++) uN1[k] = pp[k];
        }
        const u64 bhS1_2 = pack2(bhh1[rowS], 0.f);
        const u64 bhN1_2 = pack2(bhh1[rowN], 0.f);

        s_h1w[lane] = 0.f;
        __syncwarp();
        float h1own = 0.f;

        u64 H1c[8];
#pragma unroll
        for (int k = 0; k < 8; k++) H1c[k] = Z2;

        for (int it = 0; it < MNCH + 2; it++) {
            if (it >= 2) {
                const int c = it - 2;
#pragma unroll
                for (int k = 0; k < MCHUNK; k++) {
                    const int t = c * MCHUNK + k;
                    float xwS1 = s_xw[t][lane];
                    float xwN1 = s_xw[t][32 + (lane & 15)];
                    float ghS1 = dotp8b(uS1, H1c, bhS1_2, Z2);
                    float ghN1 = dotp8b(uN1, H1c, bhN1_2, Z2);
                    float s1  = sigm_a(xwS1 + ghS1);
                    float nv1 = tanh_a(fmaf(s1, ghN1, xwN1));
                    float z1  = __shfl_sync(FULLMASK, s1, 16 + (lane & 15));
                    h1own = fmaf(z1, h1own - nv1, nv1);
                    s_h1w[lane] = h1own;
                    __syncwarp();
                    {
                        ulonglong2 r0 = *(const ulonglong2*)(s_h1w);
                        ulonglong2 r1 = *(const ulonglong2*)(s_h1w + 4);
                        ulonglong2 r2 = *(const ulonglong2*)(s_h1w + 8);
                        ulonglong2 r3 = *(const ulonglong2*)(s_h1w + 12);
                        H1c[0]=r0.x; H1c[1]=r0.y; H1c[2]=r1.x; H1c[3]=r1.y;
                        H1c[4]=r2.x; H1c[5]=r2.y; H1c[6]=r3.x; H1c[7]=r3.y;
                    }
                }
            }
            __syncthreads();
        }
        if (lane < 16) g_h1fin[b * 16 + lane] = h1own;
    }
}

// ============================================================================
// K4 (merged dec, v2): batched gmem loads (ro via 2x LDG.128, d via 4x
// LDG.128), no in-loop dependent LDGs. Arithmetic order per value unchanged.
// ============================================================================
#define DEC_SMEM_BYTES ((16384 + 1024 + 2176 + 128 + 1024 + 512 + 32 + 32) * 4)
__global__ void __launch_bounds__(512) k_dec(
    const float* __restrict__ Remote,
    const float* __restrict__ w1, const float* __restrict__ b1,
    const float* __restrict__ gg, const float* __restrict__ bt,
    const float* __restrict__ w2, const float* __restrict__ b2,
    float* __restrict__ out)
{
    extern __shared__ float sm[];
    float* sw2   = sm;
    float* sb2   = sw2 + 16384;
    float* sw1   = sb2 + 1024;
    float* sb1   = sw1 + 2176;
    float* sh    = sb1 + 128;
    float* sro   = sh  + 1024;
    float* sstat = sro + 512;
    float* sgb   = sstat + 32;

    const int tid = threadIdx.x;
    {
        const float4* w24 = (const float4*)w2;
        float4* sw24 = (float4*)sw2;
        for (int i = tid; i < 4096; i += 512) sw24[i] = w24[i];
        for (int i = tid; i < 1024; i += 512) sb2[i] = b2[i];
        for (int i = tid; i < 2176; i += 512) sw1[i] = w1[i];
        if (tid < 128) sb1[tid] = b1[tid];
        if (tid < 16) { sgb[tid] = gg[tid]; sgb[16 + tid] = bt[tid]; }
    }
    __syncthreads();

    // ---- decoder layer-1 (batched loads; per-output math identical) ----
#pragma unroll
    for (int rr = 0; rr < 2; rr++) {
        const int idx = tid + rr * 512;
        const int b = idx >> 4, hh = idx & 15;
        // batched loads: ro first (longest latency), then d
        float ro8[8];
        {
            const float* rp = g_Ro + ((size_t)b * Wn + (Wn - 1)) * En;
            float4 r0 = *(const float4*)rp;
            float4 r1 = *(const float4*)(rp + 4);
            ro8[0]=r0.x; ro8[1]=r0.y; ro8[2]=r0.z; ro8[3]=r0.w;
            ro8[4]=r1.x; ro8[5]=r1.y; ro8[6]=r1.z; ro8[7]=r1.w;
        }
        float d[17];
        {
            const float4* hp = (const float4*)(g_h1fin + b * 16);
            float4 a = hp[0], bq = hp[1], c = hp[2], dd = hp[3];
            d[0]=a.x; d[1]=a.y; d[2]=a.z; d[3]=a.w;
            d[4]=bq.x; d[5]=bq.y; d[6]=bq.z; d[7]=bq.w;
            d[8]=c.x; d[9]=c.y; d[10]=c.z; d[11]=c.w;
            d[12]=dd.x; d[13]=dd.y; d[14]=dd.z; d[15]=dd.w;
        }
        d[16] = Remote[((size_t)b * Wn + (Wn - 1)) * Fn + (An + TGTn)];
        float acc = 0.f;
#pragma unroll 1
        for (int e = 0; e < 8; e++) {
            float pe = sb1[e * 16 + hh];
#pragma unroll
            for (int i = 0; i < 17; i++) pe = fmaf(d[i], sw1[e * 272 + i * 16 + hh], pe);
            acc = fmaf(ro8[e], pe, acc);
        }
        sh[idx] = acc;
        if (hh < 8) sro[b * 8 + hh] = ro8[hh];
    }
    __syncthreads();
    if (tid < 16) {
        float s = 0.f, q = 0.f;
        for (int bb = 0; bb < 64; bb++) {
            float v = sh[bb * 16 + tid];
            s += v; q = fmaf(v, v, q);
        }
        float mean = s * (1.0f / 64.0f);
        float var  = q * (1.0f / 64.0f) - mean * mean;
        sstat[tid] = mean;
        sstat[16 + tid] = rsqrtf(var + 1e-5f);
    }
    __syncthreads();
#pragma unroll
    for (int rr = 0; rr < 2; rr++) {
        const int idx = tid + rr * 512;
        const int hh = idx & 15;
        float v = sh[idx];
        v = fmaf(sgb[hh] * (v - sstat[hh]), sstat[16 + hh], sgb[16 + hh]);
        sh[idx] = (v > 0.f) ? v : (__expf(v) - 1.0f);
    }
    __syncthreads();

    // ---- decoder layer-2 ----
    const int b = blockIdx.x * 4 + (tid >> 7);
    const int o = tid & 127;

    float dh[16];
    const float4* hp = (const float4*)(sh + b * 16);
#pragma unroll
    for (int q4 = 0; q4 < 4; q4++) {
        float4 v = hp[q4];
        dh[q4*4+0]=v.x; dh[q4*4+1]=v.y; dh[q4*4+2]=v.z; dh[q4*4+3]=v.w;
    }
    float ro[8];
#pragma unroll
    for (int e = 0; e < 8; e++) ro[e] = sro[b * 8 + e];

    float acc = 0.f;
#pragma unroll 1
    for (int e = 0; e < 8; e++) {
        float pe = sb2[e * 128 + o];
        const float* wrow = sw2 + e * 2048 + o;
#pragma unroll
        for (int h = 0; h < 16; h++) pe = fmaf(dh[h], wrow[h * 128], pe);
        acc = fmaf(ro[e], pe, acc);
    }
    out[b * 128 + o] = acc;
}

// ============================================================================
// Host launcher
// ============================================================================
extern "C" void kernel_launch(void* const* d_in, const int* in_sizes, int n_in,
                              void* d_out, int out_size)
{
    (void)n_in; (void)out_size;
    const float* P[30];
    for (int i = 0; i < 30; i++) P[i] = (const float*)d_in[i];

    const float *Local = P[0], *Remote = P[1];
    const float *gWih0 = P[2], *gWhh0 = P[3], *gbih0 = P[4], *gbhh0 = P[5];
    const float *gWih1 = P[6], *gWhh1 = P[7], *gbih1 = P[8], *gbhh1 = P[9];
    const float *aew1, *aeb1, *aew2, *aeb2, *aeg, *aebt;
    const float *mdw1, *mdb1, *mdw2, *mdb2, *mdg, *mdbt;
    const float *mWih0, *mWhh0, *mbih0, *mbhh0, *mWih1, *mWhh1, *mbih1, *mbhh1;

    if (in_sizes[10] == 16384) {   // reference-signature order
        aew1 = P[10]; aeb1 = P[11]; aew2 = P[12]; aeb2 = P[13]; aeg = P[14]; aebt = P[15];
        mdw1 = P[16]; mdb1 = P[17]; mdw2 = P[18]; mdb2 = P[19]; mdg = P[20]; mdbt = P[21];
        mWih0 = P[22]; mWhh0 = P[23]; mbih0 = P[24]; mbhh0 = P[25];
        mWih1 = P[26]; mWhh1 = P[27]; mbih1 = P[28]; mbhh1 = P[29];
    } else {                        // setup_inputs dict order
        mWih0 = P[10]; mWhh0 = P[11]; mbih0 = P[12]; mbhh0 = P[13];
        mWih1 = P[14]; mWhh1 = P[15]; mbih1 = P[16]; mbhh1 = P[17];
        aew1 = P[18]; aeb1 = P[19]; aew2 = P[20]; aeb2 = P[21]; aeg = P[22]; aebt = P[23];
        mdw1 = P[24]; mdb1 = P[25]; mdw2 = P[26]; mdb2 = P[27]; mdg = P[28]; mdbt = P[29];
    }

    cudaFuncSetAttribute(k_dec, cudaFuncAttributeMaxDynamicSharedMemorySize, DEC_SMEM_BYTES);

    k_ge1<<<384, 256, GE1_SMEM_BYTES>>>(Local, Remote,
                                        gWih0, gWhh0, gbih0, gbhh0,
                                        gWih1, gWhh1, gbih1, gbhh1,
                                        aew1, aeb1);
    k_cexp2<<<256, 256>>>(aew2, aeb2, aeg, aebt, mWih0, mbih0);
    k_mixer<<<64, 96>>>(mWhh0, mbhh0, mWih1, mbih1, mWhh1, mbhh1);
    k_dec<<<16, 512, DEC_SMEM_BYTES>>>(Remote, mdw1, mdb1, mdg, mdbt,
                                       mdw2, mdb2, (float*)d_out);
}